// round 2
// baseline (speedup 1.0000x reference)
#include <cuda_runtime.h>

// TensorProductLayer: per (atom, channel) pair:
//   a=x0, b=y0, u=x1 (3), v=y1 (3), A=x2 (3x3), B=y2 (3x3)
//   out0      = a*b + u.v + <A,B>_F
//   out1[i]   = a*v[i] + b*u[i] + (u^T B)[i] + (A v)[i]
//   out2[i,j] = a*B[i,j] + b*A[i,j] + u[i]*v[j] + (A B)[i,j]
// Pure streaming, DRAM-bound (~2.0 GB total traffic).

__global__ void __launch_bounds__(256)
tp_kernel(const float* __restrict__ x0, const float* __restrict__ y0,
          const float* __restrict__ x1, const float* __restrict__ y1,
          const float* __restrict__ x2, const float* __restrict__ y2,
          float* __restrict__ o0, float* __restrict__ o1, float* __restrict__ o2,
          int total)
{
    int idx = blockIdx.x * blockDim.x + threadIdx.x;
    if (idx >= total) return;

    const float a = __ldcs(x0 + idx);
    const float b = __ldcs(y0 + idx);

    float u[3], v[3];
    {
        const float* pu = x1 + (size_t)idx * 3;
        const float* pv = y1 + (size_t)idx * 3;
#pragma unroll
        for (int i = 0; i < 3; ++i) { u[i] = __ldcs(pu + i); v[i] = __ldcs(pv + i); }
    }

    float A[9], B[9];
    {
        const float* pA = x2 + (size_t)idx * 9;
        const float* pB = y2 + (size_t)idx * 9;
#pragma unroll
        for (int i = 0; i < 9; ++i) { A[i] = __ldcs(pA + i); B[i] = __ldcs(pB + i); }
    }

    // ---- out0: scalar channel ----
    float s0 = a * b;
#pragma unroll
    for (int i = 0; i < 3; ++i) s0 = fmaf(u[i], v[i], s0);
#pragma unroll
    for (int i = 0; i < 9; ++i) s0 = fmaf(A[i], B[i], s0);
    __stcs(o0 + idx, s0);

    // ---- out1: vector channel ----
    float r1[3];
#pragma unroll
    for (int i = 0; i < 3; ++i) {
        float t = a * v[i];
        t = fmaf(b, u[i], t);
        // (u^T B)[i] = sum_d u[d] * B[d*3 + i]
#pragma unroll
        for (int d = 0; d < 3; ++d) t = fmaf(u[d], B[d * 3 + i], t);
        // (A v)[i] = sum_e A[i*3 + e] * v[e]
#pragma unroll
        for (int e = 0; e < 3; ++e) t = fmaf(A[i * 3 + e], v[e], t);
        r1[i] = t;
    }
    {
        float* po1 = o1 + (size_t)idx * 3;
#pragma unroll
        for (int i = 0; i < 3; ++i) __stcs(po1 + i, r1[i]);
    }

    // ---- out2: matrix channel ----
    {
        float* po2 = o2 + (size_t)idx * 9;
#pragma unroll
        for (int i = 0; i < 3; ++i) {
#pragma unroll
            for (int j = 0; j < 3; ++j) {
                float t = a * B[i * 3 + j];
                t = fmaf(b, A[i * 3 + j], t);
                t = fmaf(u[i], v[j], t);
                // (A B)[i,j] = sum_e A[i*3+e] * B[e*3+j]
#pragma unroll
                for (int e = 0; e < 3; ++e) t = fmaf(A[i * 3 + e], B[e * 3 + j], t);
                __stcs(po2 + i * 3 + j, t);
            }
        }
    }
}

extern "C" void kernel_launch(void* const* d_in, const int* in_sizes, int n_in,
                              void* d_out, int out_size)
{
    // Resolve inputs by size: base size s = N*C identifies rank-0; 3s rank-1; 9s rank-2.
    // First occurrence of each size = x tensor, second = y tensor. This is robust to
    // both metadata orderings (x0,y0,x1,y1,x2,y2) and (x0,x1,x2,y0,y1,y2).
    int s = in_sizes[0];
    for (int i = 1; i < n_in; ++i) if (in_sizes[i] < s) s = in_sizes[i];

    const float* X[3] = {nullptr, nullptr, nullptr};
    const float* Y[3] = {nullptr, nullptr, nullptr};
    for (int i = 0; i < n_in; ++i) {
        int rank_idx;
        if (in_sizes[i] == s)          rank_idx = 0;
        else if (in_sizes[i] == 3 * s) rank_idx = 1;
        else                           rank_idx = 2;
        if (X[rank_idx] == nullptr) X[rank_idx] = (const float*)d_in[i];
        else                        Y[rank_idx] = (const float*)d_in[i];
    }

    float* o0 = (float*)d_out;            // s elements
    float* o1 = o0 + (size_t)s;           // 3s elements
    float* o2 = o0 + (size_t)4 * s;       // 9s elements

    const int threads = 256;
    const int blocks = (s + threads - 1) / threads;
    tp_kernel<<<blocks, threads>>>(X[0], Y[0], X[1], Y[1], X[2], Y[2],
                                   o0, o1, o2, s);
}

// round 3
// speedup vs baseline: 1.4967x; 1.4967x over previous
#include <cuda_runtime.h>

// TensorProductLayer, float4-vectorized: each thread handles 4 consecutive
// (atom,channel) pairs so all loads/stores are aligned LDG.128/STG.128.
// Per pair: a=x0, b=y0, u=x1(3), v=y1(3), A=x2(9), B=y2(9)
//   out0      = a*b + u.v + <A,B>_F
//   out1[i]   = a*v[i] + b*u[i] + (u^T B)[i] + (A v)[i]
//   out2[i,j] = a*B[i,j] + b*A[i,j] + u[i]*v[j] + (A B)[i,j]

__device__ __forceinline__ void tp_pair(
    float a, float b,
    const float* __restrict__ u, const float* __restrict__ v,
    const float* __restrict__ A, const float* __restrict__ B,
    float* __restrict__ r0, float* __restrict__ r1, float* __restrict__ r2)
{
    float s0 = a * b;
#pragma unroll
    for (int i = 0; i < 3; ++i) s0 = fmaf(u[i], v[i], s0);
#pragma unroll
    for (int i = 0; i < 9; ++i) s0 = fmaf(A[i], B[i], s0);
    *r0 = s0;

#pragma unroll
    for (int i = 0; i < 3; ++i) {
        float t = a * v[i];
        t = fmaf(b, u[i], t);
#pragma unroll
        for (int d = 0; d < 3; ++d) t = fmaf(u[d], B[d * 3 + i], t);
#pragma unroll
        for (int e = 0; e < 3; ++e) t = fmaf(A[i * 3 + e], v[e], t);
        r1[i] = t;
    }

#pragma unroll
    for (int i = 0; i < 3; ++i) {
#pragma unroll
        for (int j = 0; j < 3; ++j) {
            float t = a * B[i * 3 + j];
            t = fmaf(b, A[i * 3 + j], t);
            t = fmaf(u[i], v[j], t);
#pragma unroll
            for (int e = 0; e < 3; ++e) t = fmaf(A[i * 3 + e], B[e * 3 + j], t);
            r2[i * 3 + j] = t;
        }
    }
}

__global__ void __launch_bounds__(256)
tp_kernel_v4(const float* __restrict__ x0, const float* __restrict__ y0,
             const float* __restrict__ x1, const float* __restrict__ y1,
             const float* __restrict__ x2, const float* __restrict__ y2,
             float* __restrict__ o0, float* __restrict__ o1, float* __restrict__ o2,
             int total)
{
    int t = blockIdx.x * blockDim.x + threadIdx.x;
    long long p0 = (long long)t * 4;
    if (p0 >= total) return;

    if (p0 + 4 <= total) {
        // ---- vector path: 4 pairs, all traffic as float4 ----
        float af[4], bf[4], uf[12], vf[12], Af[36], Bf[36];

        *reinterpret_cast<float4*>(af) = __ldcs(reinterpret_cast<const float4*>(x0) + t);
        *reinterpret_cast<float4*>(bf) = __ldcs(reinterpret_cast<const float4*>(y0) + t);
#pragma unroll
        for (int i = 0; i < 3; ++i) {
            reinterpret_cast<float4*>(uf)[i] = __ldcs(reinterpret_cast<const float4*>(x1) + (size_t)t * 3 + i);
            reinterpret_cast<float4*>(vf)[i] = __ldcs(reinterpret_cast<const float4*>(y1) + (size_t)t * 3 + i);
        }
#pragma unroll
        for (int i = 0; i < 9; ++i) {
            reinterpret_cast<float4*>(Af)[i] = __ldcs(reinterpret_cast<const float4*>(x2) + (size_t)t * 9 + i);
            reinterpret_cast<float4*>(Bf)[i] = __ldcs(reinterpret_cast<const float4*>(y2) + (size_t)t * 9 + i);
        }

        float r0f[4], r1f[12], r2f[36];
#pragma unroll
        for (int p = 0; p < 4; ++p) {
            tp_pair(af[p], bf[p], uf + p * 3, vf + p * 3, Af + p * 9, Bf + p * 9,
                    r0f + p, r1f + p * 3, r2f + p * 9);
        }

        __stcs(reinterpret_cast<float4*>(o0) + t, *reinterpret_cast<float4*>(r0f));
#pragma unroll
        for (int i = 0; i < 3; ++i)
            __stcs(reinterpret_cast<float4*>(o1) + (size_t)t * 3 + i, reinterpret_cast<float4*>(r1f)[i]);
#pragma unroll
        for (int i = 0; i < 9; ++i)
            __stcs(reinterpret_cast<float4*>(o2) + (size_t)t * 9 + i, reinterpret_cast<float4*>(r2f)[i]);
    } else {
        // ---- scalar tail (total % 4 != 0) ----
        for (long long p = p0; p < total; ++p) {
            float a = x0[p], b = y0[p];
            float u[3], v[3], A[9], B[9];
#pragma unroll
            for (int i = 0; i < 3; ++i) { u[i] = x1[p * 3 + i]; v[i] = y1[p * 3 + i]; }
#pragma unroll
            for (int i = 0; i < 9; ++i) { A[i] = x2[p * 9 + i]; B[i] = y2[p * 9 + i]; }
            float r0, r1[3], r2[9];
            tp_pair(a, b, u, v, A, B, &r0, r1, r2);
            o0[p] = r0;
#pragma unroll
            for (int i = 0; i < 3; ++i) o1[p * 3 + i] = r1[i];
#pragma unroll
            for (int i = 0; i < 9; ++i) o2[p * 9 + i] = r2[i];
        }
    }
}

extern "C" void kernel_launch(void* const* d_in, const int* in_sizes, int n_in,
                              void* d_out, int out_size)
{
    // Resolve inputs by element count: s = base (rank-0), 3s (rank-1), 9s (rank-2).
    // First occurrence of a size = x tensor, second = y tensor (robust to both
    // metadata orderings).
    int s = in_sizes[0];
    for (int i = 1; i < n_in; ++i) if (in_sizes[i] < s) s = in_sizes[i];

    const float* X[3] = {nullptr, nullptr, nullptr};
    const float* Y[3] = {nullptr, nullptr, nullptr};
    for (int i = 0; i < n_in; ++i) {
        int r;
        if (in_sizes[i] == s)          r = 0;
        else if (in_sizes[i] == 3 * s) r = 1;
        else                           r = 2;
        if (X[r] == nullptr) X[r] = (const float*)d_in[i];
        else                 Y[r] = (const float*)d_in[i];
    }

    float* o0 = (float*)d_out;       // s elements
    float* o1 = o0 + (size_t)s;      // 3s elements
    float* o2 = o0 + (size_t)4 * s;  // 9s elements

    const int threads = 256;
    int ngroups = (s + 3) / 4;       // 4 pairs per thread
    int blocks = (ngroups + threads - 1) / threads;
    tp_kernel_v4<<<blocks, threads>>>(X[0], Y[0], X[1], Y[1], X[2], Y[2],
                                      o0, o1, o2, s);
}

// round 4
// speedup vs baseline: 2.0728x; 1.3849x over previous
#include <cuda_runtime.h>

// TensorProductLayer, smem-staged:
//  - cooperative float4 staging of all inputs for 256 pairs/block into smem
//  - per-thread scalar compute from smem (conflict-free: strides 1,3,9 coprime to 32)
//  - results written in-place over the thread's own smem slices
//  - cooperative float4 stores to gmem
// Per pair: a=x0, b=y0, u=x1(3), v=y1(3), A=x2(9), B=y2(9)
//   out0      = a*b + u.v + <A,B>_F
//   out1[i]   = a*v[i] + b*u[i] + (u^T B)[i] + (A v)[i]
//   out2[i,j] = a*B[i,j] + b*A[i,j] + u[i]*v[j] + (A B)[i,j]

#define PB 256  // pairs per block == threads per block

__device__ __forceinline__ void tp_pair(
    float a, float b,
    const float* __restrict__ u, const float* __restrict__ v,
    const float* __restrict__ A, const float* __restrict__ B,
    float* __restrict__ r0, float* __restrict__ r1, float* __restrict__ r2)
{
    float s0 = a * b;
#pragma unroll
    for (int i = 0; i < 3; ++i) s0 = fmaf(u[i], v[i], s0);
#pragma unroll
    for (int i = 0; i < 9; ++i) s0 = fmaf(A[i], B[i], s0);
    *r0 = s0;

#pragma unroll
    for (int i = 0; i < 3; ++i) {
        float t = a * v[i];
        t = fmaf(b, u[i], t);
#pragma unroll
        for (int d = 0; d < 3; ++d) t = fmaf(u[d], B[d * 3 + i], t);
#pragma unroll
        for (int e = 0; e < 3; ++e) t = fmaf(A[i * 3 + e], v[e], t);
        r1[i] = t;
    }

#pragma unroll
    for (int i = 0; i < 3; ++i) {
#pragma unroll
        for (int j = 0; j < 3; ++j) {
            float t = a * B[i * 3 + j];
            t = fmaf(b, A[i * 3 + j], t);
            t = fmaf(u[i], v[j], t);
#pragma unroll
            for (int e = 0; e < 3; ++e) t = fmaf(A[i * 3 + e], B[e * 3 + j], t);
            r2[i * 3 + j] = t;
        }
    }
}

__global__ void __launch_bounds__(PB)
tp_kernel_smem(const float* __restrict__ x0, const float* __restrict__ y0,
               const float* __restrict__ x1, const float* __restrict__ y1,
               const float* __restrict__ x2, const float* __restrict__ y2,
               float* __restrict__ o0, float* __restrict__ o1, float* __restrict__ o2,
               int total)
{
    // smem layout (floats): sa[256] sb[256] su[768] sv[768] sA[2304] sB[2304]
    __shared__ float sm[PB * 26];
    float* sa = sm;
    float* sb = sa + PB;
    float* su = sb + PB;
    float* sv = su + PB * 3;
    float* sA = sv + PB * 3;
    float* sB = sA + PB * 9;

    const int tid = threadIdx.x;
    const long long P0 = (long long)blockIdx.x * PB;

    if (P0 + PB <= total) {
        // ================= fast path: full block =================
        // ---- stage inputs: cooperative LDG.128 ----
        {
            float4* sm4 = reinterpret_cast<float4*>(sm);
            // sa (64 f4) + sb (64 f4)
            if (tid < 128) {
                const float4* src = (tid < 64)
                    ? reinterpret_cast<const float4*>(x0) + (P0 >> 2) + tid
                    : reinterpret_cast<const float4*>(y0) + (P0 >> 2) + (tid - 64);
                sm4[tid] = __ldcs(src);
            }
            // su (192 f4) at f4-offset 128, sv (192) at 320
            {
                int i = tid;  // 0..255 covers first 256 of 384; second pass below
                const float4* b1 = reinterpret_cast<const float4*>(x1) + (P0 >> 2) * 3;
                const float4* b2 = reinterpret_cast<const float4*>(y1) + (P0 >> 2) * 3;
                // 384 total f4 for u+v
                if (i < 192) sm4[128 + i] = __ldcs(b1 + i);
                else         sm4[128 + i] = __ldcs(b2 + (i - 192));
                i += PB;
                if (i < 384) sm4[128 + i] = __ldcs(b2 + (i - 192));
            }
            // sA (576 f4) at f4-offset 512, sB (576) at 1088
            {
                const float4* bA = reinterpret_cast<const float4*>(x2) + (P0 >> 2) * 9;
                const float4* bB = reinterpret_cast<const float4*>(y2) + (P0 >> 2) * 9;
#pragma unroll
                for (int k = 0; k < 3; ++k) {
                    int i = tid + k * PB;     // 0..767 (576 used per array)
                    if (i < 576) sm4[512 + i]  = __ldcs(bA + i);
                    if (i < 576) sm4[1088 + i] = __ldcs(bB + i);
                }
            }
        }
        __syncthreads();

        // ---- compute: thread t handles pair t (own smem slices only) ----
        {
            float a = sa[tid], b = sb[tid];
            float u[3], v[3], A[9], B[9];
#pragma unroll
            for (int i = 0; i < 3; ++i) { u[i] = su[tid * 3 + i]; v[i] = sv[tid * 3 + i]; }
#pragma unroll
            for (int i = 0; i < 9; ++i) { A[i] = sA[tid * 9 + i]; B[i] = sB[tid * 9 + i]; }

            float r0, r1[3], r2[9];
            tp_pair(a, b, u, v, A, B, &r0, r1, r2);

            // overwrite own slices: sa<-r0, su<-r1, sA<-r2
            sa[tid] = r0;
#pragma unroll
            for (int i = 0; i < 3; ++i) su[tid * 3 + i] = r1[i];
#pragma unroll
            for (int i = 0; i < 9; ++i) sA[tid * 9 + i] = r2[i];
        }
        __syncthreads();

        // ---- store outputs: cooperative STG.128 ----
        {
            const float4* sm4 = reinterpret_cast<const float4*>(sm);
            // o0: 64 f4 from sa (f4-offset 0)
            if (tid < 64)
                __stcs(reinterpret_cast<float4*>(o0) + (P0 >> 2) + tid, sm4[tid]);
            // o1: 192 f4 from su (f4-offset 128)
            if (tid < 192)
                __stcs(reinterpret_cast<float4*>(o1) + (P0 >> 2) * 3 + tid, sm4[128 + tid]);
            // o2: 576 f4 from sA (f4-offset 512)
#pragma unroll
            for (int k = 0; k < 3; ++k) {
                int i = tid + k * PB;
                if (i < 576)
                    __stcs(reinterpret_cast<float4*>(o2) + (P0 >> 2) * 9 + i, sm4[512 + i]);
            }
        }
    } else {
        // ================= tail path: scalar with guards =================
        long long p = P0 + tid;
        if (p < total) {
            float a = x0[p], b = y0[p];
            float u[3], v[3], A[9], B[9];
#pragma unroll
            for (int i = 0; i < 3; ++i) { u[i] = x1[p * 3 + i]; v[i] = y1[p * 3 + i]; }
#pragma unroll
            for (int i = 0; i < 9; ++i) { A[i] = x2[p * 9 + i]; B[i] = y2[p * 9 + i]; }
            float r0, r1[3], r2[9];
            tp_pair(a, b, u, v, A, B, &r0, r1, r2);
            o0[p] = r0;
#pragma unroll
            for (int i = 0; i < 3; ++i) o1[p * 3 + i] = r1[i];
#pragma unroll
            for (int i = 0; i < 9; ++i) o2[p * 9 + i] = r2[i];
        }
    }
}

extern "C" void kernel_launch(void* const* d_in, const int* in_sizes, int n_in,
                              void* d_out, int out_size)
{
    // Resolve inputs by element count: s = base (rank-0), 3s (rank-1), 9s (rank-2).
    // First occurrence of a size = x tensor, second = y tensor (robust to both
    // metadata orderings).
    int s = in_sizes[0];
    for (int i = 1; i < n_in; ++i) if (in_sizes[i] < s) s = in_sizes[i];

    const float* X[3] = {nullptr, nullptr, nullptr};
    const float* Y[3] = {nullptr, nullptr, nullptr};
    for (int i = 0; i < n_in; ++i) {
        int r;
        if (in_sizes[i] == s)          r = 0;
        else if (in_sizes[i] == 3 * s) r = 1;
        else                           r = 2;
        if (X[r] == nullptr) X[r] = (const float*)d_in[i];
        else                 Y[r] = (const float*)d_in[i];
    }

    float* o0 = (float*)d_out;       // s elements
    float* o1 = o0 + (size_t)s;      // 3s elements
    float* o2 = o0 + (size_t)4 * s;  // 9s elements

    int blocks = (s + PB - 1) / PB;
    tp_kernel_smem<<<blocks, PB>>>(X[0], Y[0], X[1], Y[1], X[2], Y[2],
                                   o0, o1, o2, s);
}

// round 6
// speedup vs baseline: 2.1658x; 1.0449x over previous
#include <cuda_runtime.h>

// TensorProductLayer, smem-staged with cp.async (LDGSTS) input staging:
//  - cp.async.cg 16B: gmem -> smem directly (bypasses L1 + register file)
//  - per-thread scalar compute from smem (strides 1,3,9 coprime to 32: conflict-free)
//  - results overwrite the thread's own smem slices
//  - cooperative STG.128 stores
// Per pair: a=x0, b=y0, u=x1(3), v=y1(3), A=x2(9), B=y2(9)
//   out0      = a*b + u.v + <A,B>_F
//   out1[i]   = a*v[i] + b*u[i] + (u^T B)[i] + (A v)[i]
//   out2[i,j] = a*B[i,j] + b*A[i,j] + u[i]*v[j] + (A B)[i,j]

#define PB 256  // pairs per block == threads per block

__device__ __forceinline__ void cp16(float4* smem_dst, const float4* gmem_src)
{
    unsigned saddr = (unsigned)__cvta_generic_to_shared(smem_dst);
    asm volatile("cp.async.cg.shared.global [%0], [%1], 16;"
                 :: "r"(saddr), "l"(gmem_src));
}

__device__ __forceinline__ void tp_pair(
    float a, float b,
    const float* __restrict__ u, const float* __restrict__ v,
    const float* __restrict__ A, const float* __restrict__ B,
    float* __restrict__ r0, float* __restrict__ r1, float* __restrict__ r2)
{
    float s0 = a * b;
#pragma unroll
    for (int i = 0; i < 3; ++i) s0 = fmaf(u[i], v[i], s0);
#pragma unroll
    for (int i = 0; i < 9; ++i) s0 = fmaf(A[i], B[i], s0);
    *r0 = s0;

#pragma unroll
    for (int i = 0; i < 3; ++i) {
        float t = a * v[i];
        t = fmaf(b, u[i], t);
#pragma unroll
        for (int d = 0; d < 3; ++d) t = fmaf(u[d], B[d * 3 + i], t);
#pragma unroll
        for (int e = 0; e < 3; ++e) t = fmaf(A[i * 3 + e], v[e], t);
        r1[i] = t;
    }

#pragma unroll
    for (int i = 0; i < 3; ++i) {
#pragma unroll
        for (int j = 0; j < 3; ++j) {
            float t = a * B[i * 3 + j];
            t = fmaf(b, A[i * 3 + j], t);
            t = fmaf(u[i], v[j], t);
#pragma unroll
            for (int e = 0; e < 3; ++e) t = fmaf(A[i * 3 + e], B[e * 3 + j], t);
            r2[i * 3 + j] = t;
        }
    }
}

__global__ void __launch_bounds__(PB)
tp_kernel_cp(const float* __restrict__ x0, const float* __restrict__ y0,
             const float* __restrict__ x1, const float* __restrict__ y1,
             const float* __restrict__ x2, const float* __restrict__ y2,
             float* __restrict__ o0, float* __restrict__ o1, float* __restrict__ o2,
             int total)
{
    // smem layout (floats): sa[256] sb[256] su[768] sv[768] sA[2304] sB[2304]
    // f4 offsets: sa 0, sb 64, su 128, sv 320, sA 512, sB 1088 (total 1664 f4 = 26.6 KB)
    __shared__ float sm[PB * 26];
    float* sa = sm;
    float* sb = sa + PB;
    float* su = sb + PB;
    float* sv = su + PB * 3;
    float* sA = sv + PB * 3;
    float* sB = sA + PB * 9;

    const int tid = threadIdx.x;
    const long long P0 = (long long)blockIdx.x * PB;

    if (P0 + PB <= total) {
        // ================= fast path: full block =================
        // ---- stage inputs: cp.async.cg 16B, gmem -> smem direct ----
        {
            float4* sm4 = reinterpret_cast<float4*>(sm);
            const long long g = P0 >> 2;  // f4 index of block start in rank-0 space

            // sa (64 f4) + sb (64 f4): 128 ops over first 128 threads
            if (tid < 64)
                cp16(sm4 + tid, reinterpret_cast<const float4*>(x0) + g + tid);
            else if (tid < 128)
                cp16(sm4 + tid, reinterpret_cast<const float4*>(y0) + g + (tid - 64));

            // su (192 f4 @128), sv (192 f4 @320): 384 ops
            {
                const float4* b1 = reinterpret_cast<const float4*>(x1) + g * 3;
                const float4* b2 = reinterpret_cast<const float4*>(y1) + g * 3;
                int i = tid;
                if (i < 192) cp16(sm4 + 128 + i, b1 + i);
                else         cp16(sm4 + 128 + i, b2 + (i - 192));
                i += PB;
                if (i < 384) cp16(sm4 + 128 + i, b2 + (i - 192));
            }

            // sA (576 f4 @512), sB (576 f4 @1088): 1152 ops
            {
                const float4* bA = reinterpret_cast<const float4*>(x2) + g * 9;
                const float4* bB = reinterpret_cast<const float4*>(y2) + g * 9;
#pragma unroll
                for (int k = 0; k < 3; ++k) {
                    int i = tid + k * PB;   // 0..767, 576 used
                    if (i < 576) {
                        cp16(sm4 + 512 + i,  bA + i);
                        cp16(sm4 + 1088 + i, bB + i);
                    }
                }
            }

            asm volatile("cp.async.commit_group;");
            asm volatile("cp.async.wait_group 0;");
        }
        __syncthreads();

        // ---- compute: thread t handles pair t (own smem slices only) ----
        {
            float a = sa[tid], b = sb[tid];
            float u[3], v[3], A[9], B[9];
#pragma unroll
            for (int i = 0; i < 3; ++i) { u[i] = su[tid * 3 + i]; v[i] = sv[tid * 3 + i]; }
#pragma unroll
            for (int i = 0; i < 9; ++i) { A[i] = sA[tid * 9 + i]; B[i] = sB[tid * 9 + i]; }

            float r0, r1[3], r2[9];
            tp_pair(a, b, u, v, A, B, &r0, r1, r2);

            sa[tid] = r0;
#pragma unroll
            for (int i = 0; i < 3; ++i) su[tid * 3 + i] = r1[i];
#pragma unroll
            for (int i = 0; i < 9; ++i) sA[tid * 9 + i] = r2[i];
        }
        __syncthreads();

        // ---- store outputs: cooperative STG.128 ----
        {
            const float4* sm4 = reinterpret_cast<const float4*>(sm);
            const long long g = P0 >> 2;
            if (tid < 64)
                __stcs(reinterpret_cast<float4*>(o0) + g + tid, sm4[tid]);
            if (tid < 192)
                __stcs(reinterpret_cast<float4*>(o1) + g * 3 + tid, sm4[128 + tid]);
#pragma unroll
            for (int k = 0; k < 3; ++k) {
                int i = tid + k * PB;
                if (i < 576)
                    __stcs(reinterpret_cast<float4*>(o2) + g * 9 + i, sm4[512 + i]);
            }
        }
    } else {
        // ================= tail path: scalar with guards =================
        long long p = P0 + tid;
        if (p < total) {
            float a = x0[p], b = y0[p];
            float u[3], v[3], A[9], B[9];
#pragma unroll
            for (int i = 0; i < 3; ++i) { u[i] = x1[p * 3 + i]; v[i] = y1[p * 3 + i]; }
#pragma unroll
            for (int i = 0; i < 9; ++i) { A[i] = x2[p * 9 + i]; B[i] = y2[p * 9 + i]; }
            float r0, r1[3], r2[9];
            tp_pair(a, b, u, v, A, B, &r0, r1, r2);
            o0[p] = r0;
#pragma unroll
            for (int i = 0; i < 3; ++i) o1[p * 3 + i] = r1[i];
#pragma unroll
            for (int i = 0; i < 9; ++i) o2[p * 9 + i] = r2[i];
        }
    }
}

extern "C" void kernel_launch(void* const* d_in, const int* in_sizes, int n_in,
                              void* d_out, int out_size)
{
    // Resolve inputs by element count: s = base (rank-0), 3s (rank-1), 9s (rank-2).
    // First occurrence of a size = x tensor, second = y tensor (robust to both
    // metadata orderings).
    int s = in_sizes[0];
    for (int i = 1; i < n_in; ++i) if (in_sizes[i] < s) s = in_sizes[i];

    const float* X[3] = {nullptr, nullptr, nullptr};
    const float* Y[3] = {nullptr, nullptr, nullptr};
    for (int i = 0; i < n_in; ++i) {
        int r;
        if (in_sizes[i] == s)          r = 0;
        else if (in_sizes[i] == 3 * s) r = 1;
        else                           r = 2;
        if (X[r] == nullptr) X[r] = (const float*)d_in[i];
        else                 Y[r] = (const float*)d_in[i];
    }

    float* o0 = (float*)d_out;       // s elements
    float* o1 = o0 + (size_t)s;      // 3s elements
    float* o2 = o0 + (size_t)4 * s;  // 9s elements

    int blocks = (s + PB - 1) / PB;
    tp_kernel_cp<<<blocks, PB>>>(X[0], Y[0], X[1], Y[1], X[2], Y[2],
                                 o0, o1, o2, s);
}